// round 5
// baseline (speedup 1.0000x reference)
#include <cuda_runtime.h>
#include <cuda_bf16.h>
#include <mma.h>
#include <cstdint>

using namespace nvcuda;

#define N_NODES_MAX 100000
#define N_NODES_PAD 100096              // multiple of 128 for guard-free epilogue
#define N_EDGES_MAX 1600000
#define IN_F  256
#define OUT_F 128
#define SCAN_CHUNK 1024
#define MAX_SCAN_BLOCKS ((N_NODES_MAX + SCAN_CHUNK - 1) / SCAN_CHUNK)   // 98

// GEMM tiling
#define GEMM_BM 128
#define GEMM_KC 32
#define GEMM_NCHUNK (IN_F / GEMM_KC)    // 8
#define LDA_S 40                        // bf16 elements per A smem row (pad 32->40)

// ---------------- device scratch ----------------
__device__ float g_h[(size_t)N_NODES_PAD * OUT_F];     // h = x @ w (padded rows)
__device__ int   g_counts[N_NODES_MAX];
__device__ int   g_rowstart[N_NODES_MAX];
__device__ int   g_cursor[N_NODES_MAX];
__device__ int   g_sorted_src[N_EDGES_MAX];
__device__ float g_sorted_w[N_EDGES_MAX];
__device__ int   g_blocksums[MAX_SCAN_BLOCKS];
__device__ int   g_blockoffs[MAX_SCAN_BLOCKS];
// w split to bf16 hi/lo, [k][n] row-major (same layout as w)
__device__ __nv_bfloat16 g_w_hi[IN_F * OUT_F];
__device__ __nv_bfloat16 g_w_lo[IN_F * OUT_F];

__device__ __forceinline__ int clamp_idx(int v, int n) {
    v = v < 0 ? 0 : v;
    return v >= n ? n - 1 : v;
}

// ---------------- 0) prep: split w into bf16 hi/lo -------------------------
__global__ __launch_bounds__(256) void prep_w_kernel(const float* __restrict__ w)
{
    int e = blockIdx.x * blockDim.x + threadIdx.x;
    if (e >= IN_F * OUT_F) return;
    float v = w[e];
    __nv_bfloat16 hi = __float2bfloat16_rn(v);
    float rem = v - __bfloat162float(hi);
    g_w_hi[e] = hi;
    g_w_lo[e] = __float2bfloat16_rn(rem);
}

// ---------------- 1) WMMA bf16 GEMM (3-term split): g_h = x @ w ------------
// CTA: 128x128 tile, 256 threads = 8 warps (4 m-groups x 2 n-groups),
// warp tile 32x64. K processed in 8 chunks of 32 (2 wmma k-steps each).
__global__ __launch_bounds__(256) void gemm_wmma_kernel(const float* __restrict__ x, int M)
{
    __shared__ __nv_bfloat16 sA_hi[GEMM_BM][LDA_S];
    __shared__ __nv_bfloat16 sA_lo[GEMM_BM][LDA_S];
    __shared__ __nv_bfloat16 sB_hi[GEMM_KC][OUT_F];
    __shared__ __nv_bfloat16 sB_lo[GEMM_KC][OUT_F];

    const int tid = threadIdx.x;
    const int wid = tid >> 5;
    const int warp_m = wid & 3;     // 0..3 -> rows warp_m*32
    const int warp_n = wid >> 2;    // 0..1 -> cols warp_n*64
    const int block_row = blockIdx.x * GEMM_BM;

    wmma::fragment<wmma::accumulator, 16, 16, 16, float> acc[2][4];
#pragma unroll
    for (int mi = 0; mi < 2; mi++)
#pragma unroll
        for (int ni = 0; ni < 4; ni++) wmma::fill_fragment(acc[mi][ni], 0.0f);

    // A-load mapping: 4096 floats per chunk = 1024 float4; 256 thr x 4
    // idx -> row = idx/8, q = idx%8 (float4 within the 32-float row)
    for (int c = 0; c < GEMM_NCHUNK; c++) {
        const int k0 = c * GEMM_KC;
#pragma unroll
        for (int i = 0; i < 4; i++) {
            const int idx = tid * 4 + i;
            const int r = idx >> 3;
            const int q = idx & 7;
            const int row = block_row + r;
            float4 v = make_float4(0.f, 0.f, 0.f, 0.f);
            if (row < M)
                v = *reinterpret_cast<const float4*>(x + (size_t)row * IN_F + k0 + q * 4);
            __nv_bfloat16 h0 = __float2bfloat16_rn(v.x);
            __nv_bfloat16 h1 = __float2bfloat16_rn(v.y);
            __nv_bfloat16 h2 = __float2bfloat16_rn(v.z);
            __nv_bfloat16 h3 = __float2bfloat16_rn(v.w);
            sA_hi[r][q * 4 + 0] = h0;
            sA_hi[r][q * 4 + 1] = h1;
            sA_hi[r][q * 4 + 2] = h2;
            sA_hi[r][q * 4 + 3] = h3;
            sA_lo[r][q * 4 + 0] = __float2bfloat16_rn(v.x - __bfloat162float(h0));
            sA_lo[r][q * 4 + 1] = __float2bfloat16_rn(v.y - __bfloat162float(h1));
            sA_lo[r][q * 4 + 2] = __float2bfloat16_rn(v.z - __bfloat162float(h2));
            sA_lo[r][q * 4 + 3] = __float2bfloat16_rn(v.w - __bfloat162float(h3));
        }
        // B chunk: rows k0..k0+31 of g_w_hi/lo (32x128 bf16 = 8KB each)
        {
            const uint4* srch = reinterpret_cast<const uint4*>(g_w_hi + k0 * OUT_F);
            const uint4* srcl = reinterpret_cast<const uint4*>(g_w_lo + k0 * OUT_F);
            uint4* dsth = reinterpret_cast<uint4*>(&sB_hi[0][0]);
            uint4* dstl = reinterpret_cast<uint4*>(&sB_lo[0][0]);
#pragma unroll
            for (int i = 0; i < 2; i++) {
                dsth[tid + i * 256] = srch[tid + i * 256];
                dstl[tid + i * 256] = srcl[tid + i * 256];
            }
        }
        __syncthreads();

#pragma unroll
        for (int kk = 0; kk < GEMM_KC; kk += 16) {
            wmma::fragment<wmma::matrix_a, 16, 16, 16, __nv_bfloat16, wmma::row_major> a_hi[2], a_lo[2];
#pragma unroll
            for (int mi = 0; mi < 2; mi++) {
                wmma::load_matrix_sync(a_hi[mi], &sA_hi[warp_m * 32 + mi * 16][kk], LDA_S);
                wmma::load_matrix_sync(a_lo[mi], &sA_lo[warp_m * 32 + mi * 16][kk], LDA_S);
            }
#pragma unroll
            for (int ni = 0; ni < 4; ni++) {
                wmma::fragment<wmma::matrix_b, 16, 16, 16, __nv_bfloat16, wmma::row_major> b_hi, b_lo;
                wmma::load_matrix_sync(b_hi, &sB_hi[kk][warp_n * 64 + ni * 16], OUT_F);
                wmma::load_matrix_sync(b_lo, &sB_lo[kk][warp_n * 64 + ni * 16], OUT_F);
#pragma unroll
                for (int mi = 0; mi < 2; mi++) {
                    wmma::mma_sync(acc[mi][ni], a_hi[mi], b_hi, acc[mi][ni]);
                    wmma::mma_sync(acc[mi][ni], a_lo[mi], b_hi, acc[mi][ni]);
                    wmma::mma_sync(acc[mi][ni], a_hi[mi], b_lo, acc[mi][ni]);
                }
            }
        }
        __syncthreads();
    }

    // epilogue: g_h is padded to N_NODES_PAD rows -> no guards needed
#pragma unroll
    for (int mi = 0; mi < 2; mi++) {
        const int row = block_row + warp_m * 32 + mi * 16;
#pragma unroll
        for (int ni = 0; ni < 4; ni++) {
            wmma::store_matrix_sync(g_h + (size_t)row * OUT_F + warp_n * 64 + ni * 16,
                                    acc[mi][ni], OUT_F, wmma::mem_row_major);
        }
    }
}

// ---------------- 2) CSR build -----------------------------------------
__global__ void zero_counts_kernel(int n)
{
    int i = blockIdx.x * blockDim.x + threadIdx.x;
    if (i < n) g_counts[i] = 0;
}

__global__ void hist_kernel(const int* __restrict__ edst, int E, int n_nodes)
{
    int e = blockIdx.x * blockDim.x + threadIdx.x;
    if (e < E) {
        int d = clamp_idx(edst[e], n_nodes);
        atomicAdd(&g_counts[d], 1);
    }
}

__global__ __launch_bounds__(1024) void scan_pass1(int n)
{
    __shared__ int warp_sums[32];
    const int tid = threadIdx.x;
    const int i = blockIdx.x * SCAN_CHUNK + tid;
    int v = (i < n) ? g_counts[i] : 0;
    int s = v;
#pragma unroll
    for (int off = 16; off > 0; off >>= 1) s += __shfl_down_sync(0xffffffffu, s, off);
    if ((tid & 31) == 0) warp_sums[tid >> 5] = s;
    __syncthreads();
    if (tid < 32) {
        int t = warp_sums[tid];
#pragma unroll
        for (int off = 16; off > 0; off >>= 1) t += __shfl_down_sync(0xffffffffu, t, off);
        if (tid == 0) g_blocksums[blockIdx.x] = t;
    }
}

__global__ __launch_bounds__(128) void scan_pass2(int nblocks)
{
    const int tid = threadIdx.x;
    int v = (tid < nblocks) ? g_blocksums[tid] : 0;
    int x = v;
#pragma unroll
    for (int off = 1; off < 32; off <<= 1) {
        int y = __shfl_up_sync(0xffffffffu, x, off);
        if ((tid & 31) >= off) x += y;
    }
    __shared__ int ws[4];
    if ((tid & 31) == 31) ws[tid >> 5] = x;
    __syncthreads();
    int add = 0;
    for (int wlt = 0; wlt < (tid >> 5); wlt++) add += ws[wlt];
    int incl = x + add;
    if (tid < nblocks) g_blockoffs[tid] = incl - v;
}

__global__ __launch_bounds__(1024) void scan_pass3(int n)
{
    __shared__ int warp_sums[32];
    const int tid = threadIdx.x;
    const int i = blockIdx.x * SCAN_CHUNK + tid;
    int v = (i < n) ? g_counts[i] : 0;
    int x = v;
#pragma unroll
    for (int off = 1; off < 32; off <<= 1) {
        int y = __shfl_up_sync(0xffffffffu, x, off);
        if ((tid & 31) >= off) x += y;
    }
    if ((tid & 31) == 31) warp_sums[tid >> 5] = x;
    __syncthreads();
    if (tid < 32) {
        int t = warp_sums[tid];
#pragma unroll
        for (int off = 1; off < 32; off <<= 1) {
            int y = __shfl_up_sync(0xffffffffu, t, off);
            if (tid >= off) t += y;
        }
        warp_sums[tid] = t;
    }
    __syncthreads();
    int warp_off = (tid >> 5) ? warp_sums[(tid >> 5) - 1] : 0;
    int excl = x - v + warp_off + g_blockoffs[blockIdx.x];
    if (i < n) {
        g_rowstart[i] = excl;
        g_cursor[i]   = excl;
    }
}

__global__ void fill_kernel(const int* __restrict__ esrc,
                            const int* __restrict__ edst,
                            const float* __restrict__ ew, int E, int n_nodes)
{
    int e = blockIdx.x * blockDim.x + threadIdx.x;
    if (e < E) {
        int d = clamp_idx(edst[e], n_nodes);
        int pos = atomicAdd(&g_cursor[d], 1);
        if (pos >= 0 && pos < N_EDGES_MAX) {
            g_sorted_src[pos] = clamp_idx(esrc[e], n_nodes);
            g_sorted_w[pos]   = ew[e];
        }
    }
}

// ---------------- 3) gather: one warp per node, atomic-free ----------------
__global__ __launch_bounds__(256) void gather_kernel(
    const float* __restrict__ b, float* __restrict__ out, int n_nodes)
{
    const int gtid = blockIdx.x * blockDim.x + threadIdx.x;
    const int node = gtid >> 5;
    const int lane = gtid & 31;
    if (node >= n_nodes) return;

    const int start = g_rowstart[node];
    const int cnt   = g_counts[node];

    float4 acc = make_float4(0.f, 0.f, 0.f, 0.f);
    for (int j = 0; j < cnt; j++) {
        const int   s  = g_sorted_src[start + j];
        const float wt = g_sorted_w[start + j];
        const float4 v = *reinterpret_cast<const float4*>(
            g_h + (size_t)s * OUT_F + lane * 4);
        acc.x += wt * v.x;
        acc.y += wt * v.y;
        acc.z += wt * v.z;
        acc.w += wt * v.w;
    }
    const float4 bb = reinterpret_cast<const float4*>(b)[lane];
    acc.x += bb.x; acc.y += bb.y; acc.z += bb.z; acc.w += bb.w;
    reinterpret_cast<float4*>(out)[(size_t)node * 32 + lane] = acc;
}

// ---------------------------- launch ---------------------------------------
extern "C" void kernel_launch(void* const* d_in, const int* in_sizes, int n_in,
                              void* d_out, int out_size)
{
    const float* x    = (const float*)d_in[0];
    const int*   esrc = (const int*)d_in[1];
    const int*   edst = (const int*)d_in[2];
    const float* ew   = (const float*)d_in[3];
    const float* w    = (const float*)d_in[4];
    const float* b    = (const float*)d_in[5];
    float*       out  = (float*)d_out;

    const int M = in_sizes[0] / IN_F;   // 100000
    const int E = in_sizes[1];          // 1600000
    const int nscan = (M + SCAN_CHUNK - 1) / SCAN_CHUNK;

    prep_w_kernel<<<(IN_F * OUT_F + 255) / 256, 256>>>(w);
    gemm_wmma_kernel<<<(M + GEMM_BM - 1) / GEMM_BM, 256>>>(x, M);
    zero_counts_kernel<<<(M + 255) / 256, 256>>>(M);
    hist_kernel<<<(E + 255) / 256, 256>>>(edst, E, M);
    scan_pass1<<<nscan, 1024>>>(M);
    scan_pass2<<<1, 128>>>(nscan);
    scan_pass3<<<nscan, 1024>>>(M);
    fill_kernel<<<(E + 255) / 256, 256>>>(esrc, edst, ew, E, M);
    gather_kernel<<<((M * 32) + 255) / 256, 256>>>(b, out, M);
}

// round 6
// speedup vs baseline: 1.2164x; 1.2164x over previous
#include <cuda_runtime.h>
#include <cstdint>

#define N_NODES_MAX 100000
#define N_EDGES_MAX 1600000
#define IN_F  256
#define OUT_F 128
#define SCAN_CHUNK 1024
#define MAX_SCAN_BLOCKS ((N_NODES_MAX + SCAN_CHUNK - 1) / SCAN_CHUNK)   // 98

// ---------------- device scratch ----------------
__device__ float g_h[(size_t)N_NODES_MAX * OUT_F];     // 51.2 MB: h = x @ w
__device__ int   g_counts[N_NODES_MAX];
__device__ int   g_rowstart[N_NODES_MAX];
__device__ int   g_cursor[N_NODES_MAX];
__device__ int   g_sorted_src[N_EDGES_MAX];
__device__ float g_sorted_w[N_EDGES_MAX];
__device__ int   g_blocksums[MAX_SCAN_BLOCKS];
__device__ int   g_blockoffs[MAX_SCAN_BLOCKS];

__device__ __forceinline__ int clamp_idx(int v, int n) {
    v = v < 0 ? 0 : v;
    return v >= n ? n - 1 : v;
}

// ---------------- 1) SGEMM: g_h = x @ w  (M x 256) @ (256 x 128) -----------
__global__ __launch_bounds__(256) void gemm_kernel(
    const float* __restrict__ x, const float* __restrict__ w, int M)
{
    __shared__ float As[8][128];
    __shared__ float Bs[8][128];

    const int tid = threadIdx.x;
    const int block_row = blockIdx.x * 128;

    const int ty = tid >> 4;
    const int tx = tid & 15;

    const int ar = tid >> 1;
    const int ac = (tid & 1) * 4;
    const int br = tid >> 5;
    const int bc = (tid & 31) * 4;

    float acc[8][8];
#pragma unroll
    for (int i = 0; i < 8; i++)
#pragma unroll
        for (int j = 0; j < 8; j++) acc[i][j] = 0.0f;

    const int arow = block_row + ar;
    const bool arow_ok = (arow < M);
    const float* a_ptr = x + (size_t)arow * IN_F + ac;

    for (int kt = 0; kt < IN_F / 8; kt++) {
        const int kbase = kt * 8;
        float4 av = make_float4(0.f, 0.f, 0.f, 0.f);
        if (arow_ok) av = *reinterpret_cast<const float4*>(a_ptr + kbase);
        As[ac + 0][ar] = av.x;
        As[ac + 1][ar] = av.y;
        As[ac + 2][ar] = av.z;
        As[ac + 3][ar] = av.w;
        float4 bv = *reinterpret_cast<const float4*>(w + (size_t)(kbase + br) * OUT_F + bc);
        *reinterpret_cast<float4*>(&Bs[br][bc]) = bv;
        __syncthreads();

#pragma unroll
        for (int k = 0; k < 8; k++) {
            float4 a0 = *reinterpret_cast<float4*>(&As[k][ty * 8]);
            float4 a1 = *reinterpret_cast<float4*>(&As[k][ty * 8 + 4]);
            float4 b0 = *reinterpret_cast<float4*>(&Bs[k][tx * 8]);
            float4 b1 = *reinterpret_cast<float4*>(&Bs[k][tx * 8 + 4]);
            float ra[8] = {a0.x, a0.y, a0.z, a0.w, a1.x, a1.y, a1.z, a1.w};
            float rb[8] = {b0.x, b0.y, b0.z, b0.w, b1.x, b1.y, b1.z, b1.w};
#pragma unroll
            for (int i = 0; i < 8; i++)
#pragma unroll
                for (int j = 0; j < 8; j++) acc[i][j] += ra[i] * rb[j];
        }
        __syncthreads();
    }

#pragma unroll
    for (int i = 0; i < 8; i++) {
        const int row = block_row + ty * 8 + i;
        if (row < M) {
            float* o = g_h + (size_t)row * OUT_F + tx * 8;
            *reinterpret_cast<float4*>(o)     = make_float4(acc[i][0], acc[i][1], acc[i][2], acc[i][3]);
            *reinterpret_cast<float4*>(o + 4) = make_float4(acc[i][4], acc[i][5], acc[i][6], acc[i][7]);
        }
    }
}

// ---------------- 2) CSR build -----------------------------------------
__global__ void zero_counts_kernel(int n)
{
    int i = blockIdx.x * blockDim.x + threadIdx.x;
    if (i < n) g_counts[i] = 0;
}

// 4 edges per thread via int4
__global__ void hist_kernel(const int* __restrict__ edst, int E, int n_nodes)
{
    int t = blockIdx.x * blockDim.x + threadIdx.x;
    int base = t * 4;
    if (base + 3 < E) {
        int4 d4 = *reinterpret_cast<const int4*>(edst + base);
        atomicAdd(&g_counts[clamp_idx(d4.x, n_nodes)], 1);
        atomicAdd(&g_counts[clamp_idx(d4.y, n_nodes)], 1);
        atomicAdd(&g_counts[clamp_idx(d4.z, n_nodes)], 1);
        atomicAdd(&g_counts[clamp_idx(d4.w, n_nodes)], 1);
    } else {
        for (int e = base; e < E; e++)
            atomicAdd(&g_counts[clamp_idx(edst[e], n_nodes)], 1);
    }
}

__global__ __launch_bounds__(1024) void scan_pass1(int n)
{
    __shared__ int warp_sums[32];
    const int tid = threadIdx.x;
    const int i = blockIdx.x * SCAN_CHUNK + tid;
    int v = (i < n) ? g_counts[i] : 0;
    int s = v;
#pragma unroll
    for (int off = 16; off > 0; off >>= 1) s += __shfl_down_sync(0xffffffffu, s, off);
    if ((tid & 31) == 0) warp_sums[tid >> 5] = s;
    __syncthreads();
    if (tid < 32) {
        int t = warp_sums[tid];
#pragma unroll
        for (int off = 16; off > 0; off >>= 1) t += __shfl_down_sync(0xffffffffu, t, off);
        if (tid == 0) g_blocksums[blockIdx.x] = t;
    }
}

__global__ __launch_bounds__(128) void scan_pass2(int nblocks)
{
    const int tid = threadIdx.x;
    int v = (tid < nblocks) ? g_blocksums[tid] : 0;
    int x = v;
#pragma unroll
    for (int off = 1; off < 32; off <<= 1) {
        int y = __shfl_up_sync(0xffffffffu, x, off);
        if ((tid & 31) >= off) x += y;
    }
    __shared__ int ws[4];
    if ((tid & 31) == 31) ws[tid >> 5] = x;
    __syncthreads();
    int add = 0;
    for (int wlt = 0; wlt < (tid >> 5); wlt++) add += ws[wlt];
    int incl = x + add;
    if (tid < nblocks) g_blockoffs[tid] = incl - v;
}

__global__ __launch_bounds__(1024) void scan_pass3(int n)
{
    __shared__ int warp_sums[32];
    const int tid = threadIdx.x;
    const int i = blockIdx.x * SCAN_CHUNK + tid;
    int v = (i < n) ? g_counts[i] : 0;
    int x = v;
#pragma unroll
    for (int off = 1; off < 32; off <<= 1) {
        int y = __shfl_up_sync(0xffffffffu, x, off);
        if ((tid & 31) >= off) x += y;
    }
    if ((tid & 31) == 31) warp_sums[tid >> 5] = x;
    __syncthreads();
    if (tid < 32) {
        int t = warp_sums[tid];
#pragma unroll
        for (int off = 1; off < 32; off <<= 1) {
            int y = __shfl_up_sync(0xffffffffu, t, off);
            if (tid >= off) t += y;
        }
        warp_sums[tid] = t;
    }
    __syncthreads();
    int warp_off = (tid >> 5) ? warp_sums[(tid >> 5) - 1] : 0;
    int excl = x - v + warp_off + g_blockoffs[blockIdx.x];
    if (i < n) {
        g_rowstart[i] = excl;
        g_cursor[i]   = excl;
    }
}

__global__ void fill_kernel(const int* __restrict__ esrc,
                            const int* __restrict__ edst,
                            const float* __restrict__ ew, int E, int n_nodes)
{
    int e = blockIdx.x * blockDim.x + threadIdx.x;
    if (e < E) {
        int d = clamp_idx(edst[e], n_nodes);
        int pos = atomicAdd(&g_cursor[d], 1);
        if (pos >= 0 && pos < N_EDGES_MAX) {
            g_sorted_src[pos] = clamp_idx(esrc[e], n_nodes);
            g_sorted_w[pos]   = ew[e];
        }
    }
}

// ---------------- 3) gather: one warp per node, unrolled x4 ----------------
__global__ __launch_bounds__(256) void gather_kernel(
    const float* __restrict__ b, float* __restrict__ out, int n_nodes)
{
    const int gtid = blockIdx.x * blockDim.x + threadIdx.x;
    const int node = gtid >> 5;
    const int lane = gtid & 31;
    if (node >= n_nodes) return;

    const int start = g_rowstart[node];
    const int cnt   = g_counts[node];
    const float* hbase = g_h + (size_t)lane * 4;

    float4 acc0 = make_float4(0.f, 0.f, 0.f, 0.f);
    float4 acc1 = make_float4(0.f, 0.f, 0.f, 0.f);

    int j = 0;
    for (; j + 4 <= cnt; j += 4) {
        const int   s0 = g_sorted_src[start + j + 0];
        const int   s1 = g_sorted_src[start + j + 1];
        const int   s2 = g_sorted_src[start + j + 2];
        const int   s3 = g_sorted_src[start + j + 3];
        const float w0 = g_sorted_w[start + j + 0];
        const float w1 = g_sorted_w[start + j + 1];
        const float w2 = g_sorted_w[start + j + 2];
        const float w3 = g_sorted_w[start + j + 3];
        const float4 v0 = *reinterpret_cast<const float4*>(hbase + (size_t)s0 * OUT_F);
        const float4 v1 = *reinterpret_cast<const float4*>(hbase + (size_t)s1 * OUT_F);
        const float4 v2 = *reinterpret_cast<const float4*>(hbase + (size_t)s2 * OUT_F);
        const float4 v3 = *reinterpret_cast<const float4*>(hbase + (size_t)s3 * OUT_F);
        acc0.x += w0 * v0.x; acc0.y += w0 * v0.y; acc0.z += w0 * v0.z; acc0.w += w0 * v0.w;
        acc1.x += w1 * v1.x; acc1.y += w1 * v1.y; acc1.z += w1 * v1.z; acc1.w += w1 * v1.w;
        acc0.x += w2 * v2.x; acc0.y += w2 * v2.y; acc0.z += w2 * v2.z; acc0.w += w2 * v2.w;
        acc1.x += w3 * v3.x; acc1.y += w3 * v3.y; acc1.z += w3 * v3.z; acc1.w += w3 * v3.w;
    }
    for (; j < cnt; j++) {
        const int   s  = g_sorted_src[start + j];
        const float wt = g_sorted_w[start + j];
        const float4 v = *reinterpret_cast<const float4*>(hbase + (size_t)s * OUT_F);
        acc0.x += wt * v.x; acc0.y += wt * v.y; acc0.z += wt * v.z; acc0.w += wt * v.w;
    }

    const float4 bb = reinterpret_cast<const float4*>(b)[lane];
    float4 r;
    r.x = acc0.x + acc1.x + bb.x;
    r.y = acc0.y + acc1.y + bb.y;
    r.z = acc0.z + acc1.z + bb.z;
    r.w = acc0.w + acc1.w + bb.w;
    reinterpret_cast<float4*>(out)[(size_t)node * 32 + lane] = r;
}

// ---------------------------- launch ---------------------------------------
extern "C" void kernel_launch(void* const* d_in, const int* in_sizes, int n_in,
                              void* d_out, int out_size)
{
    const float* x    = (const float*)d_in[0];
    const int*   esrc = (const int*)d_in[1];
    const int*   edst = (const int*)d_in[2];
    const float* ew   = (const float*)d_in[3];
    const float* w    = (const float*)d_in[4];
    const float* b    = (const float*)d_in[5];
    float*       out  = (float*)d_out;

    const int M = in_sizes[0] / IN_F;   // 100000
    const int E = in_sizes[1];          // 1600000
    const int nscan = (M + SCAN_CHUNK - 1) / SCAN_CHUNK;

    // lazy one-time creation of side stream + events (host resources only;
    // happens during the eager correctness call, reused under graph capture)
    static cudaStream_t s_side = nullptr;
    static cudaEvent_t  e_fork = nullptr, e_join = nullptr;
    if (!s_side) {
        cudaStreamCreateWithFlags(&s_side, cudaStreamNonBlocking);
        cudaEventCreateWithFlags(&e_fork, cudaEventDisableTiming);
        cudaEventCreateWithFlags(&e_join, cudaEventDisableTiming);
    }

    // fork: CSR build on side stream, GEMM on main (legacy) stream
    cudaEventRecord(e_fork, 0);
    cudaStreamWaitEvent(s_side, e_fork, 0);

    gemm_kernel<<<(M + 127) / 128, 256>>>(x, w, M);

    zero_counts_kernel<<<(M + 255) / 256, 256, 0, s_side>>>(M);
    hist_kernel<<<((E + 3) / 4 + 255) / 256, 256, 0, s_side>>>(edst, E, M);
    scan_pass1<<<nscan, 1024, 0, s_side>>>(M);
    scan_pass2<<<1, 128, 0, s_side>>>(nscan);
    scan_pass3<<<nscan, 1024, 0, s_side>>>(M);
    fill_kernel<<<(E + 255) / 256, 256, 0, s_side>>>(esrc, edst, ew, E, M);

    // join: gather needs both GEMM (main) and CSR (side)
    cudaEventRecord(e_join, s_side);
    cudaStreamWaitEvent(0, e_join, 0);

    gather_kernel<<<((M * 32) + 255) / 256, 256>>>(b, out, M);
}